// round 2
// baseline (speedup 1.0000x reference)
#include <cuda_runtime.h>
#include <math.h>

#define BATCH 128
#define NFEAT 128

// ---------------- scratch (static device arrays; no allocation) ----------------
// g_h3 (177 MB) aliases g_h1 (236 MB): conv3 reads g_h2 and writes h3; g_h1 is
// dead by then. Total static scratch: ~442 MB.
__device__ float g_h1[(size_t)BATCH * NFEAT * 60 * 60];   // 236 MB (also holds h3)
__device__ float g_h2[(size_t)BATCH * NFEAT * 56 * 56];   // 206 MB
#define g_h3 g_h1
__device__ float g_mbf[BATCH * NFEAT];                    // per-(b,f) spatial max
__device__ int   g_bmax[BATCH * 169];                     // per-(b,block) max (float bits)
__device__ int   g_ccount[BATCH * NFEAT];                 // candidate count per map
__device__ int2  g_cand[BATCH * NFEAT * 8];               // (y,x) candidates per map
__device__ int   g_scount[BATCH];
__device__ int4  g_surv[BATCH * 1024];                    // f, y, x, value-bits

// ---------------- conv1: 1->128 ch, 5x5, 64->60, ReLU ----------------
__global__ __launch_bounds__(256)
void k_conv1(const float* __restrict__ X, const float* __restrict__ w1,
             const float* __restrict__ b1)
{
    __shared__ float sx[8 * 64];
    __shared__ float sw[128 * 25];
    __shared__ float sb[128];
    const int b  = blockIdx.y;
    const int y0 = blockIdx.x * 4;
    const int t  = threadIdx.x;
    const float* Xb = X + (size_t)b * 4096;

    for (int i = t; i < 8 * 64; i += 256) {
        int yy = i >> 6, xx = i & 63;
        sx[i] = Xb[(y0 + yy) * 64 + xx];
    }
    for (int i = t; i < 3200; i += 256) sw[i] = w1[i];
    if (t < 128) sb[t] = b1[t];
    __syncthreads();

    if (t >= 240) return;
    const int yy = t / 60, x = t % 60;

    float patch[25];
#pragma unroll
    for (int ky = 0; ky < 5; ky++)
#pragma unroll
        for (int kx = 0; kx < 5; kx++)
            patch[ky * 5 + kx] = sx[(yy + ky) * 64 + x + kx];

    float* hb = g_h1 + (size_t)b * NFEAT * 3600 + (size_t)(y0 + yy) * 60 + x;
#pragma unroll 4
    for (int f = 0; f < 128; f++) {
        float acc = sb[f];
        const float* wf = &sw[f * 25];
#pragma unroll
        for (int k = 0; k < 25; k++) acc = fmaf(patch[k], wf[k], acc);
        hb[(size_t)f * 3600] = fmaxf(acc, 0.f);
    }
}

// ---------------- conv2/conv3 core: implicit-GEMM, 128x128 tile, BK=8 ----------------
// GEMM: C[fo][p] = sum_k W[fo][k] * Im2col[k][p],  k = ci*25 + ky*5 + kx, K = 3200
template <int IH, int IW, int OH, int OW, bool RELU>
__device__ __forceinline__ void conv_body(const float* __restrict__ in,
                                          const float* __restrict__ w,
                                          const float* __restrict__ bias,
                                          float* __restrict__ out)
{
    constexpr int NPIX = OH * OW;
    constexpr int K    = 3200;
    constexpr int BK   = 8;
    constexpr int NK   = K / BK;   // 400

    __shared__ float As[2][BK][128];
    __shared__ float Bs[2][BK][128];

    const int t  = threadIdx.x;
    const int b  = blockIdx.z;
    const int n0 = blockIdx.x * 128;

    const float* inb = in + (size_t)b * 128 * IH * IW;

    // B-operand (im2col gather) lane setup
    const int nB  = t & 127;
    const int kk0 = t >> 7;             // 0 or 1
    const int p   = n0 + nB;
    const bool pv = p < NPIX;
    const int py  = pv ? (p / OW) : 0;
    const int px  = pv ? (p % OW) : 0;

    // A-operand (weights) lane setup: one float4 per thread per chunk
    const int foA = t >> 1;             // 0..127
    const int cA  = t & 1;              // float4 column within BK=8

    const int tn = t & 15;
    const int tm = t >> 4;

    float acc[8][8];
#pragma unroll
    for (int i = 0; i < 8; i++)
#pragma unroll
        for (int j = 0; j < 8; j++) acc[i][j] = 0.f;

    float4 pa;
    float  pb[4];

    // ---- initial chunk (k0 = 0) ----
    pa = *reinterpret_cast<const float4*>(w + (size_t)foA * K + cA * 4);
#pragma unroll
    for (int j = 0; j < 4; j++) {
        int k  = kk0 + 2 * j;
        int ci = k / 25;
        int r  = k - ci * 25;
        int ky = r / 5;
        int kx = r - ky * 5;
        pb[j] = inb[ci * (IH * IW) + (py + ky) * IW + (px + kx)];
    }
#pragma unroll
    for (int i = 0; i < 4; i++) As[0][cA * 4 + i][foA] = ((const float*)&pa)[i];
#pragma unroll
    for (int j = 0; j < 4; j++) Bs[0][kk0 + 2 * j][nB] = pb[j];
    __syncthreads();

    int buf = 0;
#pragma unroll 1
    for (int it = 0; it < NK; ++it) {
        const bool has = (it + 1) < NK;
        const int k0n  = (it + 1) * BK;
        if (has) {
            pa = *reinterpret_cast<const float4*>(w + (size_t)foA * K + k0n + cA * 4);
#pragma unroll
            for (int j = 0; j < 4; j++) {
                int k  = k0n + kk0 + 2 * j;
                int ci = k / 25;
                int r  = k - ci * 25;
                int ky = r / 5;
                int kx = r - ky * 5;
                pb[j] = inb[ci * (IH * IW) + (py + ky) * IW + (px + kx)];
            }
        }
#pragma unroll
        for (int kk = 0; kk < BK; ++kk) {
            float4 A0 = *reinterpret_cast<const float4*>(&As[buf][kk][tm * 4]);
            float4 A1 = *reinterpret_cast<const float4*>(&As[buf][kk][64 + tm * 4]);
            float4 B0 = *reinterpret_cast<const float4*>(&Bs[buf][kk][tn * 4]);
            float4 B1 = *reinterpret_cast<const float4*>(&Bs[buf][kk][64 + tn * 4]);
            float a[8] = {A0.x, A0.y, A0.z, A0.w, A1.x, A1.y, A1.z, A1.w};
            float bb[8] = {B0.x, B0.y, B0.z, B0.w, B1.x, B1.y, B1.z, B1.w};
#pragma unroll
            for (int i = 0; i < 8; i++)
#pragma unroll
                for (int j = 0; j < 8; j++)
                    acc[i][j] = fmaf(a[i], bb[j], acc[i][j]);
        }
        if (has) {
#pragma unroll
            for (int i = 0; i < 4; i++) As[buf ^ 1][cA * 4 + i][foA] = ((const float*)&pa)[i];
#pragma unroll
            for (int j = 0; j < 4; j++) Bs[buf ^ 1][kk0 + 2 * j][nB] = pb[j];
            __syncthreads();
            buf ^= 1;
        }
    }

    // ---- epilogue: bias (+ReLU), float4 stores ----
    float* outb = out + (size_t)b * 128 * NPIX;
#pragma unroll
    for (int i = 0; i < 8; i++) {
        const int fo = (i < 4) ? (tm * 4 + i) : (64 + tm * 4 + (i - 4));
        const float bv = bias[fo];
#pragma unroll
        for (int jg = 0; jg < 2; jg++) {
            const int nn = n0 + ((jg == 0) ? (tn * 4) : (64 + tn * 4));
            if (nn < NPIX) {  // NPIX % 4 == 0 and nn % 4 == 0 -> whole float4 valid
                float4 v;
                v.x = acc[i][jg * 4 + 0] + bv;
                v.y = acc[i][jg * 4 + 1] + bv;
                v.z = acc[i][jg * 4 + 2] + bv;
                v.w = acc[i][jg * 4 + 3] + bv;
                if (RELU) {
                    v.x = fmaxf(v.x, 0.f); v.y = fmaxf(v.y, 0.f);
                    v.z = fmaxf(v.z, 0.f); v.w = fmaxf(v.w, 0.f);
                }
                *reinterpret_cast<float4*>(&outb[(size_t)fo * NPIX + nn]) = v;
            }
        }
    }
}

__global__ __launch_bounds__(256, 2)
void k_conv2(const float* __restrict__ w, const float* __restrict__ bias)
{
    conv_body<60, 60, 56, 56, true>(g_h1, w, bias, g_h2);
}

__global__ __launch_bounds__(256, 2)
void k_conv3(const float* __restrict__ w, const float* __restrict__ bias)
{
    conv_body<56, 56, 52, 52, false>(g_h2, w, bias, g_h3);
}

// ---------------- sparsity pipeline ----------------
__global__ void k_zero()
{
    int i = blockIdx.x * 256 + threadIdx.x;
    if (i < BATCH * 169)   g_bmax[i] = 0;  // == __float_as_int(0.f)
    if (i < BATCH)         g_scount[i] = 0;
    if (i < BATCH * NFEAT) g_ccount[i] = 0;
}

// Fused per-(b,f): spatial max over 52x52, record candidate positions (ties
// kept), and contribute to the per-(b, 4x4 block) max across channels.
// One full read of h3 instead of three.
__global__ __launch_bounds__(256)
void k_maxcand()
{
    const int bf = blockIdx.x;
    const int b  = bf >> 7;
    const float* m = g_h3 + (size_t)bf * 2704;
    const int t = threadIdx.x;
    float v = -3.4e38f;
    // strided read; keep values for second pass in registers (11 per thread)
    float loc[11];
#pragma unroll
    for (int j = 0; j < 11; j++) {
        int i = t + j * 256;
        float x = (i < 2704) ? m[i] : -3.4e38f;
        loc[j] = x;
        v = fmaxf(v, x);
    }
#pragma unroll
    for (int o = 16; o > 0; o >>= 1) v = fmaxf(v, __shfl_xor_sync(~0u, v, o));
    __shared__ float red[8];
    __shared__ float smax;
    if ((t & 31) == 0) red[t >> 5] = v;
    __syncthreads();
    if (t < 8) {
        v = red[t];
#pragma unroll
        for (int o = 4; o > 0; o >>= 1) v = fmaxf(v, __shfl_xor_sync(0xffu, v, o));
        if (t == 0) { smax = v; g_mbf[bf] = v; }
    }
    __syncthreads();
    const float mx = smax;
    if (!(mx > 0.f)) return;  // non-positive spatial max can never beat block zeros
    const int mxi = __float_as_int(mx);
    // second pass from registers: record candidates + block max
#pragma unroll
    for (int j = 0; j < 11; j++) {
        int i = t + j * 256;
        if (i < 2704 && loc[j] == mx) {
            int y = i / 52, x = i - y * 52;
            int ci = atomicAdd(&g_ccount[bf], 1);
            if (ci < 8) g_cand[bf * 8 + ci] = make_int2(y, x);
            atomicMax(&g_bmax[b * 169 + (y >> 2) * 13 + (x >> 2)], mxi);
        }
    }
}

// Resolve survivors: candidates whose value equals their block's max.
__global__ __launch_bounds__(128)
void k_surv()
{
    const int b = blockIdx.x;
    const int f = threadIdx.x;
    const int bf = b * NFEAT + f;
    const float mx = g_mbf[bf];
    if (!(mx > 0.f)) return;
    const int mxi = __float_as_int(mx);
    int nc = g_ccount[bf];
    if (nc > 8) nc = 8;
    for (int ci = 0; ci < nc; ci++) {
        int2 c = g_cand[bf * 8 + ci];
        if (g_bmax[b * 169 + (c.x >> 2) * 13 + (c.y >> 2)] == mxi) {
            int idx = atomicAdd(&g_scount[b], 1);
            if (idx < 1024) g_surv[b * 1024 + idx] = make_int4(f, c.x, c.y, mxi);
        }
    }
}

// ---------------- transposed conv (13x13 stamps) + sigmoid ----------------
__global__ __launch_bounds__(256)
void k_deconv(const float* __restrict__ wd, const float* __restrict__ bd,
              float* __restrict__ out)
{
    __shared__ float slog[4096];
    __shared__ int4  ss[1024];
    const int b = blockIdx.x;
    const int t = threadIdx.x;
    for (int i = t; i < 4096; i += 256) slog[i] = 0.f;
    int n = g_scount[b];
    if (n > 1024) n = 1024;
    for (int i = t; i < n; i += 256) ss[i] = g_surv[b * 1024 + i];
    __syncthreads();

    for (int idx = t; idx < n * 169; idx += 256) {
        int s  = idx / 169;
        int kp = idx - s * 169;
        int4 sv = ss[s];
        int dy = kp / 13, dx = kp - dy * 13;
        float wv = wd[sv.x * 169 + kp];
        atomicAdd(&slog[(sv.y + dy) * 64 + (sv.z + dx)], __int_as_float(sv.w) * wv);
    }
    __syncthreads();

    const float b0 = bd[0];
    for (int pp = t; pp < 4096; pp += 256) {
        float z = slog[pp] + b0;
        out[(size_t)b * 4096 + pp] = 1.f / (1.f + expf(-z));
    }
}

// ---------------- launch ----------------
extern "C" void kernel_launch(void* const* d_in, const int* in_sizes, int n_in,
                              void* d_out, int out_size)
{
    const float* X  = (const float*)d_in[0];
    const float* w1 = (const float*)d_in[1];
    const float* b1 = (const float*)d_in[2];
    const float* w2 = (const float*)d_in[3];
    const float* b2 = (const float*)d_in[4];
    const float* w3 = (const float*)d_in[5];
    const float* b3 = (const float*)d_in[6];
    const float* wd = (const float*)d_in[7];
    const float* bd = (const float*)d_in[8];
    float* out = (float*)d_out;

    (void)in_sizes; (void)n_in; (void)out_size;

    k_conv1<<<dim3(15, BATCH), 256>>>(X, w1, b1);
    k_conv2<<<dim3(25, 1, BATCH), 256>>>(w2, b2);   // 3136 pixels -> 25 tiles of 128
    k_zero<<<64, 256>>>();
    k_conv3<<<dim3(22, 1, BATCH), 256>>>(w3, b3);   // 2704 pixels -> 22 tiles of 128
    k_maxcand<<<BATCH * NFEAT, 256>>>();
    k_surv<<<BATCH, 128>>>();
    k_deconv<<<BATCH, 256>>>(wd, bd, out);
}